// round 7
// baseline (speedup 1.0000x reference)
#include <cuda_runtime.h>

#define NN 50000
#define NE 800000
#define C  64
#define NIN 16

// ---------------- scratch (device globals; no allocation allowed) ----------------
__device__ __align__(16) float g_xn[NN * C];     // node features [N][64]
__device__ __align__(16) float g_yn[NN * C];     // Kni @ xn      [N][64]
__device__ float4 g_coords[NN];                  // KNclose @ xn, padded to 4
__device__ float  g_w[NE];                       // edge weights
__device__ int    g_cnt[NN];
__device__ int    g_rowstart[NN + 1];
__device__ int    g_cursor[NN];
__device__ __align__(8) int2 g_ent[2 * NE];      // .x = edge id | signbit, .y = other endpoint
__device__ float g_sums[C], g_sumsq[C], g_mean[C], g_rstd[C];

// ---------------- K0: xn = KNopen @ xn_in; zero counters ----------------
__global__ void k0_open(const float* __restrict__ xnin, const float* __restrict__ KNopen) {
    __shared__ float sK[C * NIN];
    for (int t = threadIdx.x; t < C * NIN; t += blockDim.x) sK[t] = KNopen[t];
    __syncthreads();
    int n = blockIdx.x * blockDim.x + threadIdx.x;
    if (n >= NN) return;
    g_cnt[n] = 0;
    float in[NIN];
#pragma unroll
    for (int f = 0; f < NIN; f++) in[f] = xnin[f * NN + n];
    float4* outp = (float4*)&g_xn[n * C];
#pragma unroll
    for (int q = 0; q < 16; q++) {
        float a0 = 0.f, a1 = 0.f, a2 = 0.f, a3 = 0.f;
#pragma unroll
        for (int f = 0; f < NIN; f++) {
            a0 += sK[(4 * q + 0) * NIN + f] * in[f];
            a1 += sK[(4 * q + 1) * NIN + f] * in[f];
            a2 += sK[(4 * q + 2) * NIN + f] * in[f];
            a3 += sK[(4 * q + 3) * NIN + f] * in[f];
        }
        outp[q] = make_float4(a0, a1, a2, a3);
    }
}

// ---------------- CSR build ----------------
__global__ void khist(const int* __restrict__ iInd, const int* __restrict__ jInd) {
    int e = blockIdx.x * 256 + threadIdx.x;   // NE divisible by 256
    atomicAdd(&g_cnt[iInd[e]], 1);
    atomicAdd(&g_cnt[jInd[e]], 1);
}

__device__ __forceinline__ int warpIncScan(int v) {
    int lane = threadIdx.x & 31;
#pragma unroll
    for (int o = 1; o < 32; o <<= 1) {
        int t = __shfl_up_sync(0xffffffffu, v, o);
        if (lane >= o) v += t;
    }
    return v;
}

__global__ void kscan() {
    __shared__ int wsum[32];
    int tid = threadIdx.x, lane = tid & 31, wid = tid >> 5;
    int carry = 0;
    for (int base = 0; base < NN; base += 1024) {
        int idx = base + tid;
        int v = (idx < NN) ? g_cnt[idx] : 0;
        int inc = warpIncScan(v);
        if (lane == 31) wsum[wid] = inc;
        __syncthreads();
        if (wid == 0) { int t2 = wsum[lane]; t2 = warpIncScan(t2); wsum[lane] = t2; }
        __syncthreads();
        int off = carry + (wid > 0 ? wsum[wid - 1] : 0);
        int excl = off + inc - v;
        if (idx < NN) { g_rowstart[idx] = excl; g_cursor[idx] = excl; }
        carry += wsum[31];
        __syncthreads();
    }
    if (tid == 0) g_rowstart[NN] = carry;
}

__global__ void kfill(const int* __restrict__ iInd, const int* __restrict__ jInd) {
    int e = blockIdx.x * 256 + threadIdx.x;
    int i = iInd[e], j = jInd[e];
    int p1 = atomicAdd(&g_cursor[i], 1);
    g_ent[p1] = make_int2(e, j);
    int p2 = atomicAdd(&g_cursor[j], 1);
    g_ent[p2] = make_int2((int)((unsigned)e | 0x80000000u), i);
}

// ---------------- K1: yn = KN[l] @ xn, coords/XX = KNclose @ xn ----------------
// block = 256 threads, tile = 16 nodes. NN divisible by 16.
__global__ void k1_gemm(const float* __restrict__ KNl, const float* __restrict__ KNc,
                        float* __restrict__ xxOut, float* __restrict__ xnOut, int doYn) {
    __shared__ float sX[16 * 68];
    __shared__ float sM[67 * 68];
    int t = threadIdx.x;
    if (blockIdx.x == 0 && t < C) { g_sums[t] = 0.f; g_sumsq[t] = 0.f; }
    int base = blockIdx.x * 16;
    for (int idx = t; idx < 16 * C; idx += 256)
        sX[(idx >> 6) * 68 + (idx & 63)] = g_xn[base * C + idx];
    if (doYn)
        for (int idx = t; idx < C * C; idx += 256)
            sM[(idx >> 6) * 68 + (idx & 63)] = KNl[idx];
    for (int idx = t; idx < 3 * C; idx += 256)
        sM[(64 + (idx >> 6)) * 68 + (idx & 63)] = KNc[idx];
    __syncthreads();
    int node = t & 15, rg = t >> 4;
    const float4* xp = (const float4*)&sX[node * 68];
    float4 xv[16];
#pragma unroll
    for (int q = 0; q < 16; q++) xv[q] = xp[q];
    int gn = base + node;
#pragma unroll
    for (int rr = 0; rr < 5; rr++) {
        int r = rg + rr * 16;
        if (r >= 67) break;
        if (r < 64 && !doYn) continue;
        const float4* mp = (const float4*)&sM[r * 68];
        float acc = 0.f;
#pragma unroll
        for (int q = 0; q < 16; q++) {
            float4 m = mp[q];
            acc += m.x * xv[q].x + m.y * xv[q].y + m.z * xv[q].z + m.w * xv[q].w;
        }
        if (r < 64) {
            g_yn[gn * C + r] = acc;
        } else {
            int cr = r - 64;
            ((float*)g_coords)[gn * 4 + cr] = acc;
            __stcs(&xxOut[cr * NN + gn], acc);          // write-once output: evict-first
            if (xnOut) __stcs(&xnOut[cr * NN + gn], acc);
        }
    }
    if (rg == 0) ((float*)g_coords)[gn * 4 + 3] = 0.f;
}

// ---------------- K2: edge pass A — w + per-channel stats ----------------
// warp per edge (grid-stride, 2-way unrolled for MLP). lane owns channels 2l, 2l+1.
__global__ void k2_edge(const int* __restrict__ iInd, const int* __restrict__ jInd) {
    __shared__ float shS[C], shQ[C];
    int t = threadIdx.x;
    if (t < C) { shS[t] = 0.f; shQ[t] = 0.f; }
    __syncthreads();
    int lane = t & 31;
    int gw = (blockIdx.x * blockDim.x + t) >> 5;
    int nw = (gridDim.x * blockDim.x) >> 5;
    int c = lane * 2;
    float sx = 0.f, sy = 0.f, qx = 0.f, qy = 0.f;
    for (int e = gw; e < NE; e += 2 * nw) {
        int e2 = e + nw;
        bool has2 = (e2 < NE);
        // issue both gather chains before consuming either
        int i1 = __ldg(&iInd[e]);
        int j1 = __ldg(&jInd[e]);
        int i2 = has2 ? __ldg(&iInd[e2]) : 0;
        int j2 = has2 ? __ldg(&jInd[e2]) : 0;
        float4 ci1 = __ldg(&g_coords[i1]), cj1 = __ldg(&g_coords[j1]);
        float2 yi1 = __ldg((const float2*)&g_yn[i1 * C + c]);
        float2 yj1 = __ldg((const float2*)&g_yn[j1 * C + c]);
        float4 ci2, cj2; float2 yi2, yj2;
        if (has2) {
            ci2 = __ldg(&g_coords[i2]); cj2 = __ldg(&g_coords[j2]);
            yi2 = __ldg((const float2*)&g_yn[i2 * C + c]);
            yj2 = __ldg((const float2*)&g_yn[j2 * C + c]);
        }
        {
            float dx = ci1.x - cj1.x, dy = ci1.y - cj1.y, dz = ci1.z - cj1.z;
            float we = __expf(-10.f * (dx * dx + dy * dy + dz * dz));
            if (lane == 0) g_w[e] = we;
            float ax = we * (yi1.x - yj1.x), ay = we * (yi1.y - yj1.y);
            sx += ax; sy += ay; qx += ax * ax; qy += ay * ay;
        }
        if (has2) {
            float dx = ci2.x - cj2.x, dy = ci2.y - cj2.y, dz = ci2.z - cj2.z;
            float we = __expf(-10.f * (dx * dx + dy * dy + dz * dz));
            if (lane == 0) g_w[e2] = we;
            float ax = we * (yi2.x - yj2.x), ay = we * (yi2.y - yj2.y);
            sx += ax; sy += ay; qx += ax * ax; qy += ay * ay;
        }
    }
    atomicAdd(&shS[c], sx);     atomicAdd(&shS[c + 1], sy);
    atomicAdd(&shQ[c], qx);     atomicAdd(&shQ[c + 1], qy);
    __syncthreads();
    if (t < C) { atomicAdd(&g_sums[t], shS[t]); atomicAdd(&g_sumsq[t], shQ[t]); }
}

// ---------------- K3: finalize instance-norm stats ----------------
__global__ void k3_stats() {
    int t = threadIdx.x;
    if (t < C) {
        float m = g_sums[t] * (1.f / NE);
        float v = g_sumsq[t] * (1.f / NE) - m * m;
        g_mean[t] = m;
        g_rstd[t] = rsqrtf(v + 1e-5f);
    }
}

// ---------------- K4: node pass — accumulate z column, Kni^T matvec, xn update ----------------
// warp per node; software-pipelined edge walk (prefetch next entry + yn row).
// sK holds -H * Kni so the epilogue is pure FMA.
// __launch_bounds__(256, 8): cap regs at 32 so 8 blocks (2048 thr) fit per SM
// — doubles resident warps for the latency-bound gather loop.
__global__ void __launch_bounds__(256, 8) k4_node(const float* __restrict__ KNl) {
    __shared__ float sK[C * C];
    __shared__ float sAcc[8][C];
    int t = threadIdx.x, lane = t & 31, wib = t >> 5;
    for (int idx = t; idx < C * C; idx += 256) sK[idx] = -0.1f * KNl[idx];
    int c = lane * 2;
    float rx = g_rstd[c], ry = g_rstd[c + 1];
    float mxrx = g_mean[c] * rx, myry = g_mean[c + 1] * ry;   // fold norm: (a-m)*r = a*r - m*r
    __syncthreads();
    int gw = (blockIdx.x * 256 + t) >> 5;
    int nw = (gridDim.x * 256) >> 5;
    for (int n = gw; n < NN; n += nw) {
        float2 self = __ldg((const float2*)&g_yn[n * C + c]);
        float accx = 0.f, accy = 0.f;
        int k0 = g_rowstart[n], k1 = g_rowstart[n + 1];
        if (k0 < k1) {
            // prologue: fetch entry k0
            int2 ent = __ldg(&g_ent[k0]);
            float we = __ldg(&g_w[(unsigned)ent.x & 0x7fffffffu]);
            float2 yo = __ldg((const float2*)&g_yn[ent.y * C + c]);
            float sgn = (ent.x < 0) ? -1.f : 1.f;
            for (int k = k0 + 1; k < k1; k++) {
                // prefetch next entry while computing current
                int2 ent2 = __ldg(&g_ent[k]);
                float we2 = __ldg(&g_w[(unsigned)ent2.x & 0x7fffffffu]);
                float2 yo2 = __ldg((const float2*)&g_yn[ent2.y * C + c]);
                float swe = sgn * we;
                float ax = swe * (self.x - yo.x);     // == w*(yn_i - yn_j) either way
                float ay = swe * (self.y - yo.y);
                float ex = fmaxf(0.f, fmaf(ax, rx, -mxrx));
                float ey = fmaxf(0.f, fmaf(ay, ry, -myry));
                accx = fmaf(swe, ex, accx);           // +w*xe at i, -w*xe at j
                accy = fmaf(swe, ey, accy);
                we = we2; yo = yo2; sgn = (ent2.x < 0) ? -1.f : 1.f;
            }
            float swe = sgn * we;
            float ax = swe * (self.x - yo.x);
            float ay = swe * (self.y - yo.y);
            float ex = fmaxf(0.f, fmaf(ax, rx, -mxrx));
            float ey = fmaxf(0.f, fmaf(ay, ry, -myry));
            accx = fmaf(swe, ex, accx);
            accy = fmaf(swe, ey, accy);
        }
        sAcc[wib][c] = accx; sAcc[wib][c + 1] = accy;
        __syncwarp();
        float2 x = *(float2*)&g_xn[n * C + c];        // x += (-H*K)^T @ acc
#pragma unroll 8
        for (int f = 0; f < C; f++) {
            float af = sAcc[wib][f];
            float2 kf = *(const float2*)&sK[f * C + c];   // (-H*Kni)^T
            x.x = fmaf(af, kf.x, x.x);
            x.y = fmaf(af, kf.y, x.y);
        }
        *(float2*)&g_xn[n * C + c] = x;
        __syncwarp();
    }
}

// ---------------- K5: xe_out = KEclose @ relu(norm(last-layer Ai)) ----------------
// block = 8 warps, tile = 32 edges; staged coalesced writes. NE divisible by 32.
__global__ void k5_eout(const int* __restrict__ iInd, const int* __restrict__ jInd,
                        const float* __restrict__ KEclose, float* __restrict__ outXe) {
    __shared__ float sOut[16][33];
    int t = threadIdx.x, lane = t & 31, wid = t >> 5;
    int c = lane * 2;
    float ke0[16], ke1[16];
#pragma unroll
    for (int o = 0; o < 16; o++) {
        ke0[o] = __ldg(&KEclose[o * C + c]);
        ke1[o] = __ldg(&KEclose[o * C + c + 1]);
    }
    float rx = g_rstd[c], ry = g_rstd[c + 1];
    float mxrx = g_mean[c] * rx, myry = g_mean[c + 1] * ry;
    for (int tb = blockIdx.x * 32; tb < NE; tb += gridDim.x * 32) {
#pragma unroll
        for (int sub = 0; sub < 4; sub++) {
            int e = tb + wid * 4 + sub;
            int i = __ldg(&iInd[e]);
            int j = __ldg(&jInd[e]);
            float we = __ldg(&g_w[e]);
            float2 yi = __ldg((const float2*)&g_yn[i * C + c]);
            float2 yj = __ldg((const float2*)&g_yn[j * C + c]);
            float ax = we * (yi.x - yj.x), ay = we * (yi.y - yj.y);
            float ex = fmaxf(0.f, fmaf(ax, rx, -mxrx));
            float ey = fmaxf(0.f, fmaf(ay, ry, -myry));
            float p[16];
#pragma unroll
            for (int o = 0; o < 16; o++) p[o] = fmaf(ke0[o], ex, ke1[o] * ey);
#pragma unroll
            for (int off = 16; off >= 1; off >>= 1)
#pragma unroll
                for (int o = 0; o < 16; o++) p[o] += __shfl_xor_sync(0xffffffffu, p[o], off);
            if (lane == 0) {
#pragma unroll
                for (int o = 0; o < 16; o++) sOut[o][wid * 4 + sub] = p[o];
            }
        }
        __syncthreads();
        int row = t >> 5, col = t & 31;
        __stcs(&outXe[row * NE + tb + col],       sOut[row][col]);       // 51 MB write-once
        __stcs(&outXe[(row + 8) * NE + tb + col], sOut[row + 8][col]);   // keep L2 for gathers
        __syncthreads();
    }
}

// ---------------- host ----------------
extern "C" void kernel_launch(void* const* d_in, const int* in_sizes, int n_in,
                              void* d_out, int out_size) {
    const float* xn_in   = (const float*)d_in[0];
    // d_in[1] (xe) and d_in[5] (KEopen) are dead: overwritten before use.
    const int*   iInd    = (const int*)d_in[2];
    const int*   jInd    = (const int*)d_in[3];
    const float* KNopen  = (const float*)d_in[4];
    const float* KNclose = (const float*)d_in[6];
    const float* KEclose = (const float*)d_in[7];
    const float* KN      = (const float*)d_in[8];

    float* out    = (float*)d_out;
    float* out_xn = out;                       // [1,3,NN]
    float* out_xe = out + 3 * NN;              // [1,16,NE]
    float* out_xx = out + 3 * NN + 16 * NE;    // [4,1,3,NN]

    k0_open<<<(NN + 255) / 256, 256>>>(xn_in, KNopen);
    khist<<<NE / 256, 256>>>(iInd, jInd);
    kscan<<<1, 1024>>>();
    kfill<<<NE / 256, 256>>>(iInd, jInd);

    for (int l = 0; l < 3; l++) {
        k1_gemm<<<NN / 16, 256>>>(KN + l * C * C, KNclose, out_xx + l * 3 * NN, nullptr, 1);
        k2_edge<<<888, 256>>>(iInd, jInd);
        k3_stats<<<1, 64>>>();
        if (l == 2) k5_eout<<<1184, 256>>>(iInd, jInd, KEclose, out_xe);
        k4_node<<<1184, 256>>>(KN + l * C * C);   // full-occupancy wave (8 blocks/SM)
    }
    // final: XX[3] == xn_out = KNclose @ xn
    k1_gemm<<<NN / 16, 256>>>(KNclose, KNclose, out_xx + 9 * NN, out_xn, 0);
}

// round 14
// speedup vs baseline: 1.1228x; 1.1228x over previous
#include <cuda_runtime.h>

#define NN 50000
#define NE 800000
#define C  64
#define NIN 16

// ---------------- scratch (device globals; no allocation allowed) ----------------
__device__ __align__(16) float g_xn[NN * C];     // node features [N][64]
__device__ __align__(16) float g_yn[NN * C];     // Kni @ xn      [N][64]
__device__ float4 g_coords[NN];                  // KNclose @ xn, padded to 4
__device__ float  g_w[NE];                       // edge weights
__device__ int    g_cnt[NN];
__device__ int    g_rowstart[NN + 1];
__device__ int    g_cursor[NN];
__device__ __align__(8) int2 g_ent[2 * NE];      // .x = edge id | signbit, .y = other endpoint
__device__ __align__(8) int2 g_entOW[2 * NE];    // .x = other, .y = bits(sgn*w)  (per layer)
__device__ float g_sums[C], g_sumsq[C];

// ---------------- K0: xn = KNopen @ xn_in; zero counters ----------------
__global__ void k0_open(const float* __restrict__ xnin, const float* __restrict__ KNopen) {
    __shared__ float sK[C * NIN];
    for (int t = threadIdx.x; t < C * NIN; t += blockDim.x) sK[t] = KNopen[t];
    __syncthreads();
    int n = blockIdx.x * blockDim.x + threadIdx.x;
    if (n >= NN) return;
    g_cnt[n] = 0;
    float in[NIN];
#pragma unroll
    for (int f = 0; f < NIN; f++) in[f] = xnin[f * NN + n];
    float4* outp = (float4*)&g_xn[n * C];
#pragma unroll
    for (int q = 0; q < 16; q++) {
        float a0 = 0.f, a1 = 0.f, a2 = 0.f, a3 = 0.f;
#pragma unroll
        for (int f = 0; f < NIN; f++) {
            a0 += sK[(4 * q + 0) * NIN + f] * in[f];
            a1 += sK[(4 * q + 1) * NIN + f] * in[f];
            a2 += sK[(4 * q + 2) * NIN + f] * in[f];
            a3 += sK[(4 * q + 3) * NIN + f] * in[f];
        }
        outp[q] = make_float4(a0, a1, a2, a3);
    }
}

// ---------------- CSR build ----------------
__global__ void khist(const int* __restrict__ iInd, const int* __restrict__ jInd) {
    int e = blockIdx.x * 256 + threadIdx.x;   // NE divisible by 256
    atomicAdd(&g_cnt[iInd[e]], 1);
    atomicAdd(&g_cnt[jInd[e]], 1);
}

__device__ __forceinline__ int warpIncScan(int v) {
    int lane = threadIdx.x & 31;
#pragma unroll
    for (int o = 1; o < 32; o <<= 1) {
        int t = __shfl_up_sync(0xffffffffu, v, o);
        if (lane >= o) v += t;
    }
    return v;
}

__global__ void kscan() {
    __shared__ int wsum[32];
    int tid = threadIdx.x, lane = tid & 31, wid = tid >> 5;
    int carry = 0;
    for (int base = 0; base < NN; base += 1024) {
        int idx = base + tid;
        int v = (idx < NN) ? g_cnt[idx] : 0;
        int inc = warpIncScan(v);
        if (lane == 31) wsum[wid] = inc;
        __syncthreads();
        if (wid == 0) { int t2 = wsum[lane]; t2 = warpIncScan(t2); wsum[lane] = t2; }
        __syncthreads();
        int off = carry + (wid > 0 ? wsum[wid - 1] : 0);
        int excl = off + inc - v;
        if (idx < NN) { g_rowstart[idx] = excl; g_cursor[idx] = excl; }
        carry += wsum[31];
        __syncthreads();
    }
    if (tid == 0) g_rowstart[NN] = carry;
}

__global__ void kfill(const int* __restrict__ iInd, const int* __restrict__ jInd) {
    int e = blockIdx.x * 256 + threadIdx.x;
    int i = iInd[e], j = jInd[e];
    int p1 = atomicAdd(&g_cursor[i], 1);
    g_ent[p1] = make_int2(e, j);
    int p2 = atomicAdd(&g_cursor[j], 1);
    g_ent[p2] = make_int2((int)((unsigned)e | 0x80000000u), i);
}

// ---------------- KW: per-entry (other, sgn*w) — hoists k4's random w gather ----
__global__ void kwent() {
    int k = blockIdx.x * 256 + threadIdx.x;    // 2*NE divisible by 256
    int2 ent = __ldg(&g_ent[k]);
    float we = __ldg(&g_w[(unsigned)ent.x & 0x7fffffffu]);
    float swe = (ent.x < 0) ? -we : we;
    g_entOW[k] = make_int2(ent.y, __float_as_int(swe));
}

// ---------------- K1: yn = KN[l] @ xn, coords/XX = KNclose @ xn ----------------
// block = 256 threads, tile = 16 nodes. NN divisible by 16.
__global__ void k1_gemm(const float* __restrict__ KNl, const float* __restrict__ KNc,
                        float* __restrict__ xxOut, float* __restrict__ xnOut, int doYn) {
    __shared__ float sX[16 * 68];
    __shared__ float sM[67 * 68];
    int t = threadIdx.x;
    if (blockIdx.x == 0 && t < C) { g_sums[t] = 0.f; g_sumsq[t] = 0.f; }
    int base = blockIdx.x * 16;
    for (int idx = t; idx < 16 * C; idx += 256)
        sX[(idx >> 6) * 68 + (idx & 63)] = g_xn[base * C + idx];
    if (doYn)
        for (int idx = t; idx < C * C; idx += 256)
            sM[(idx >> 6) * 68 + (idx & 63)] = KNl[idx];
    for (int idx = t; idx < 3 * C; idx += 256)
        sM[(64 + (idx >> 6)) * 68 + (idx & 63)] = KNc[idx];
    __syncthreads();
    int node = t & 15, rg = t >> 4;
    const float4* xp = (const float4*)&sX[node * 68];
    float4 xv[16];
#pragma unroll
    for (int q = 0; q < 16; q++) xv[q] = xp[q];
    int gn = base + node;
#pragma unroll
    for (int rr = 0; rr < 5; rr++) {
        int r = rg + rr * 16;
        if (r >= 67) break;
        if (r < 64 && !doYn) continue;
        const float4* mp = (const float4*)&sM[r * 68];
        float acc = 0.f;
#pragma unroll
        for (int q = 0; q < 16; q++) {
            float4 m = mp[q];
            acc += m.x * xv[q].x + m.y * xv[q].y + m.z * xv[q].z + m.w * xv[q].w;
        }
        if (r < 64) {
            g_yn[gn * C + r] = acc;
        } else {
            int cr = r - 64;
            ((float*)g_coords)[gn * 4 + cr] = acc;
            __stcs(&xxOut[cr * NN + gn], acc);          // write-once output: evict-first
            if (xnOut) __stcs(&xnOut[cr * NN + gn], acc);
        }
    }
    if (rg == 0) ((float*)g_coords)[gn * 4 + 3] = 0.f;
}

// ---------------- K2: edge pass A — w + per-channel stats ----------------
// HALF-WARP per edge (grid-stride, 2-way unrolled). lane h=t&15 owns 4 channels.
__global__ void k2_edge(const int* __restrict__ iInd, const int* __restrict__ jInd) {
    __shared__ float shS[C], shQ[C];
    int t = threadIdx.x;
    if (t < C) { shS[t] = 0.f; shQ[t] = 0.f; }
    __syncthreads();
    int h = t & 15;
    int c = h * 4;
    int ghw = (blockIdx.x * blockDim.x + t) >> 4;
    int nhw = (gridDim.x * blockDim.x) >> 4;
    float4 s = make_float4(0.f, 0.f, 0.f, 0.f);
    float4 q = make_float4(0.f, 0.f, 0.f, 0.f);
    for (int e = ghw; e < NE; e += 2 * nhw) {
        int e2 = e + nhw;
        bool has2 = (e2 < NE);
        int i1 = __ldg(&iInd[e]),  j1 = __ldg(&jInd[e]);
        int i2 = has2 ? __ldg(&iInd[e2]) : 0;
        int j2 = has2 ? __ldg(&jInd[e2]) : 0;
        float4 ci1 = __ldg(&g_coords[i1]), cj1 = __ldg(&g_coords[j1]);
        float4 yi1 = __ldg((const float4*)&g_yn[i1 * C + c]);
        float4 yj1 = __ldg((const float4*)&g_yn[j1 * C + c]);
        float4 ci2, cj2, yi2, yj2;
        if (has2) {
            ci2 = __ldg(&g_coords[i2]); cj2 = __ldg(&g_coords[j2]);
            yi2 = __ldg((const float4*)&g_yn[i2 * C + c]);
            yj2 = __ldg((const float4*)&g_yn[j2 * C + c]);
        }
        {
            float dx = ci1.x - cj1.x, dy = ci1.y - cj1.y, dz = ci1.z - cj1.z;
            float we = __expf(-10.f * (dx * dx + dy * dy + dz * dz));
            if (h == 0) g_w[e] = we;
            float a0 = we * (yi1.x - yj1.x), a1 = we * (yi1.y - yj1.y);
            float a2 = we * (yi1.z - yj1.z), a3 = we * (yi1.w - yj1.w);
            s.x += a0; s.y += a1; s.z += a2; s.w += a3;
            q.x = fmaf(a0, a0, q.x); q.y = fmaf(a1, a1, q.y);
            q.z = fmaf(a2, a2, q.z); q.w = fmaf(a3, a3, q.w);
        }
        if (has2) {
            float dx = ci2.x - cj2.x, dy = ci2.y - cj2.y, dz = ci2.z - cj2.z;
            float we = __expf(-10.f * (dx * dx + dy * dy + dz * dz));
            if (h == 0) g_w[e2] = we;
            float a0 = we * (yi2.x - yj2.x), a1 = we * (yi2.y - yj2.y);
            float a2 = we * (yi2.z - yj2.z), a3 = we * (yi2.w - yj2.w);
            s.x += a0; s.y += a1; s.z += a2; s.w += a3;
            q.x = fmaf(a0, a0, q.x); q.y = fmaf(a1, a1, q.y);
            q.z = fmaf(a2, a2, q.z); q.w = fmaf(a3, a3, q.w);
        }
    }
    atomicAdd(&shS[c + 0], s.x); atomicAdd(&shS[c + 1], s.y);
    atomicAdd(&shS[c + 2], s.z); atomicAdd(&shS[c + 3], s.w);
    atomicAdd(&shQ[c + 0], q.x); atomicAdd(&shQ[c + 1], q.y);
    atomicAdd(&shQ[c + 2], q.z); atomicAdd(&shQ[c + 3], q.w);
    __syncthreads();
    if (t < C) { atomicAdd(&g_sums[t], shS[t]); atomicAdd(&g_sumsq[t], shQ[t]); }
}

// ---------------- K4: node pass — HALF-WARP per node, float4 channels ----------------
// Per entry: one broadcast 8B entOW load + one LDG.128 yo gather (16 lanes = 256B).
// Two nodes per warp = 2 independent chains; plus 1-deep rolling prefetch.
// NOTE: halves diverge (different trip counts) -> sync with per-half mask only.
__global__ void __launch_bounds__(256, 6) k4_node(const float* __restrict__ KNl) {
    __shared__ float sK[C * C];
    __shared__ float sAcc[16][C];               // per half-warp
    __shared__ float sMean[C], sRstd[C];
    int t = threadIdx.x;
    int hw = t >> 4;                            // half-warp in block (0..15)
    int h = t & 15;                             // lane in half-warp
    int c = h * 4;
    unsigned hmask = 0xFFFFu << (t & 16);       // own half's lane mask
    for (int idx = t; idx < C * C; idx += 256) sK[idx] = -0.1f * KNl[idx];
    if (t < C) {
        float m = g_sums[t] * (1.f / NE);
        float v = g_sumsq[t] * (1.f / NE) - m * m;
        sMean[t] = m;
        sRstd[t] = rsqrtf(v + 1e-5f);
    }
    __syncthreads();
    float4 r4 = *(const float4*)&sRstd[c];
    float4 m4 = *(const float4*)&sMean[c];
    float4 mr4 = make_float4(m4.x * r4.x, m4.y * r4.y, m4.z * r4.z, m4.w * r4.w);
    int ghw = (blockIdx.x * 256 + t) >> 4;
    int nhw = (gridDim.x * 256) >> 4;
    for (int n = ghw; n < NN; n += nhw) {
        float4 self = __ldg((const float4*)&g_yn[n * C + c]);
        float4 acc = make_float4(0.f, 0.f, 0.f, 0.f);
        int k0 = g_rowstart[n], k1 = g_rowstart[n + 1];
        if (k0 < k1) {
            int2 ow = __ldg(&g_entOW[k0]);
            float4 yo = __ldg((const float4*)&g_yn[ow.x * C + c]);
            float swe = __int_as_float(ow.y);
            for (int k = k0 + 1; k < k1; k++) {
                int2 ow2 = __ldg(&g_entOW[k]);
                float4 yo2 = __ldg((const float4*)&g_yn[ow2.x * C + c]);
                float a0 = swe * (self.x - yo.x), a1 = swe * (self.y - yo.y);
                float a2 = swe * (self.z - yo.z), a3 = swe * (self.w - yo.w);
                float e0 = fmaxf(0.f, fmaf(a0, r4.x, -mr4.x));
                float e1 = fmaxf(0.f, fmaf(a1, r4.y, -mr4.y));
                float e2 = fmaxf(0.f, fmaf(a2, r4.z, -mr4.z));
                float e3 = fmaxf(0.f, fmaf(a3, r4.w, -mr4.w));
                acc.x = fmaf(swe, e0, acc.x); acc.y = fmaf(swe, e1, acc.y);
                acc.z = fmaf(swe, e2, acc.z); acc.w = fmaf(swe, e3, acc.w);
                yo = yo2; swe = __int_as_float(ow2.y);
            }
            float a0 = swe * (self.x - yo.x), a1 = swe * (self.y - yo.y);
            float a2 = swe * (self.z - yo.z), a3 = swe * (self.w - yo.w);
            float e0 = fmaxf(0.f, fmaf(a0, r4.x, -mr4.x));
            float e1 = fmaxf(0.f, fmaf(a1, r4.y, -mr4.y));
            float e2 = fmaxf(0.f, fmaf(a2, r4.z, -mr4.z));
            float e3 = fmaxf(0.f, fmaf(a3, r4.w, -mr4.w));
            acc.x = fmaf(swe, e0, acc.x); acc.y = fmaf(swe, e1, acc.y);
            acc.z = fmaf(swe, e2, acc.z); acc.w = fmaf(swe, e3, acc.w);
        }
        *(float4*)&sAcc[hw][c] = acc;
        __syncwarp(hmask);
        float4 x = *(const float4*)&g_xn[n * C + c];   // x += (-H*K)^T @ acc
#pragma unroll 8
        for (int f = 0; f < C; f++) {
            float af = sAcc[hw][f];
            float4 kf = *(const float4*)&sK[f * C + c];   // (-H*Kni)^T
            x.x = fmaf(af, kf.x, x.x); x.y = fmaf(af, kf.y, x.y);
            x.z = fmaf(af, kf.z, x.z); x.w = fmaf(af, kf.w, x.w);
        }
        *(float4*)&g_xn[n * C + c] = x;
        __syncwarp(hmask);
    }
}

// ---------------- K5: xe_out = KEclose @ relu(norm(last-layer Ai)) ----------------
// block = 8 warps, tile = 32 edges; staged coalesced writes. Stats in prologue.
__global__ void k5_eout(const int* __restrict__ iInd, const int* __restrict__ jInd,
                        const float* __restrict__ KEclose, float* __restrict__ outXe) {
    __shared__ float sOut[16][33];
    __shared__ float sMean[C], sRstd[C];
    int t = threadIdx.x, lane = t & 31, wid = t >> 5;
    if (t < C) {
        float m = g_sums[t] * (1.f / NE);
        float v = g_sumsq[t] * (1.f / NE) - m * m;
        sMean[t] = m;
        sRstd[t] = rsqrtf(v + 1e-5f);
    }
    int c = lane * 2;
    float ke0[16], ke1[16];
#pragma unroll
    for (int o = 0; o < 16; o++) {
        ke0[o] = __ldg(&KEclose[o * C + c]);
        ke1[o] = __ldg(&KEclose[o * C + c + 1]);
    }
    __syncthreads();
    float rx = sRstd[c], ry = sRstd[c + 1];
    float mxrx = sMean[c] * rx, myry = sMean[c + 1] * ry;
    for (int tb = blockIdx.x * 32; tb < NE; tb += gridDim.x * 32) {
#pragma unroll
        for (int sub = 0; sub < 4; sub++) {
            int e = tb + wid * 4 + sub;
            int i = __ldg(&iInd[e]);
            int j = __ldg(&jInd[e]);
            float we = __ldg(&g_w[e]);
            float2 yi = __ldg((const float2*)&g_yn[i * C + c]);
            float2 yj = __ldg((const float2*)&g_yn[j * C + c]);
            float ax = we * (yi.x - yj.x), ay = we * (yi.y - yj.y);
            float ex = fmaxf(0.f, fmaf(ax, rx, -mxrx));
            float ey = fmaxf(0.f, fmaf(ay, ry, -myry));
            float p[16];
#pragma unroll
            for (int o = 0; o < 16; o++) p[o] = fmaf(ke0[o], ex, ke1[o] * ey);
#pragma unroll
            for (int off = 16; off >= 1; off >>= 1)
#pragma unroll
                for (int o = 0; o < 16; o++) p[o] += __shfl_xor_sync(0xffffffffu, p[o], off);
            if (lane == 0) {
#pragma unroll
                for (int o = 0; o < 16; o++) sOut[o][wid * 4 + sub] = p[o];
            }
        }
        __syncthreads();
        int row = t >> 5, col = t & 31;
        __stcs(&outXe[row * NE + tb + col],       sOut[row][col]);       // 51 MB write-once
        __stcs(&outXe[(row + 8) * NE + tb + col], sOut[row + 8][col]);   // keep L2 for gathers
        __syncthreads();
    }
}

// ---------------- host ----------------
extern "C" void kernel_launch(void* const* d_in, const int* in_sizes, int n_in,
                              void* d_out, int out_size) {
    const float* xn_in   = (const float*)d_in[0];
    // d_in[1] (xe) and d_in[5] (KEopen) are dead: overwritten before use.
    const int*   iInd    = (const int*)d_in[2];
    const int*   jInd    = (const int*)d_in[3];
    const float* KNopen  = (const float*)d_in[4];
    const float* KNclose = (const float*)d_in[6];
    const float* KEclose = (const float*)d_in[7];
    const float* KN      = (const float*)d_in[8];

    float* out    = (float*)d_out;
    float* out_xn = out;                       // [1,3,NN]
    float* out_xe = out + 3 * NN;              // [1,16,NE]
    float* out_xx = out + 3 * NN + 16 * NE;    // [4,1,3,NN]

    // Order chosen so my 4th launch (ncu capture slot -s 5 -c 1) is hot k2_edge.
    k0_open<<<(NN + 255) / 256, 256>>>(xn_in, KNopen);
    khist<<<NE / 256, 256>>>(iInd, jInd);
    k1_gemm<<<NN / 16, 256>>>(KN, KNclose, out_xx, nullptr, 1);          // l=0
    k2_edge<<<888, 256>>>(iInd, jInd);                                   // l=0  <- profiled
    kscan<<<1, 1024>>>();
    kfill<<<NE / 256, 256>>>(iInd, jInd);
    kwent<<<2 * NE / 256, 256>>>();                                      // l=0
    k4_node<<<1184, 256>>>(KN);                                          // l=0

    for (int l = 1; l < 3; l++) {
        k1_gemm<<<NN / 16, 256>>>(KN + l * C * C, KNclose, out_xx + l * 3 * NN, nullptr, 1);
        k2_edge<<<888, 256>>>(iInd, jInd);
        kwent<<<2 * NE / 256, 256>>>();
        if (l == 2) k5_eout<<<1184, 256>>>(iInd, jInd, KEclose, out_xe);
        k4_node<<<1184, 256>>>(KN + l * C * C);
    }
    // final: XX[3] == xn_out = KNclose @ xn
    k1_gemm<<<NN / 16, 256>>>(KNclose, KNclose, out_xx + 9 * NN, out_xn, 0);
}